// round 9
// baseline (speedup 1.0000x reference)
#include <cuda_runtime.h>
#include <math.h>

#define B 64
#define T 512
#define E 256
#define U 256
#define Z 1024      /* 4*U */
#define CHUNK 64
#define NCHUNK (T / CHUNK)   /* 8 */

__device__ __forceinline__ float sigm(float v) { return 1.0f / (1.0f + expf(-v)); }

// Floor model (confirmed R1-R8): 33.5MB mandatory writes / ~3.85 TB/s shared
// L2-write-commit wall ~= 8.7us + ~1.95us fixed graph gap. This round removes
// the last non-write latency from the critical path: STORE FIRST, CHECK LATER.
//
// One CTA per (batch, 64-timestep chunk), 512 CTAs. Keras masked-LSTM:
// state updates ONLY where token == 0 (mask True); elsewhere h/c carry and
// out[b,t] is the carried h1. Every CTA unconditionally zero-fills its chunk
// (correct in the common no-active-token case) while its token int4 load is
// in flight; only CTAs whose prefix [0, t_end) contains a zero token replay
// the masked LSTM and overwrite (exact for arbitrary inputs). Ordering of the
// zero stores vs. the overwrite stores is guaranteed by the replay path's
// block-wide __syncthreads() before its first output store.
__global__ __launch_bounds__(256)
void lstm_fused_kernel(const int*   __restrict__ x,
                       const float* __restrict__ emb,
                       const float* __restrict__ k0,
                       const float* __restrict__ r0,
                       const float* __restrict__ b0,
                       const float* __restrict__ k1,
                       const float* __restrict__ r1,
                       const float* __restrict__ b1,
                       float*       __restrict__ out)
{
    const int b     = blockIdx.x >> 3;
    const int chunk = blockIdx.x & (NCHUNK - 1);
    const int t0    = chunk * CHUNK;
    const int t_end = t0 + CHUNK;
    const int j     = threadIdx.x;            // 0..255

    // Kick off the token load immediately (result consumed after the stores).
    const int n4 = t_end >> 2;                 // 16..128 int4 words
    int4 tv = make_int4(1, 1, 1, 1);
    if (j < n4)
        tv = reinterpret_cast<const int4*>(x + (size_t)b * T)[j];

    // Unconditional zero-fill of this chunk: 64*256 floats = 4096 f4 / 256 thr.
    // These stores issue while the token load is still in flight.
    {
        const float4 zv = make_float4(0.f, 0.f, 0.f, 0.f);
        float4* dst = reinterpret_cast<float4*>(out + (size_t)b * T * U + (size_t)t0 * U)
                      + j;
        #pragma unroll
        for (int i = 0; i < 16; i++)
            __stcs(dst + i * 256, zv);
        if (chunk == NCHUNK - 1 && j < U / 4) {
            float4* hdst = reinterpret_cast<float4*>(out + (size_t)B * T * U + (size_t)b * U);
            __stcs(hdst + j, zv);
        }
    }

    // Now resolve the predicate: any zero token in [0, t_end)?
    const int pred = (j < n4) ? ((tv.x == 0) | (tv.y == 0) | (tv.z == 0) | (tv.w == 0)) : 0;
    const int any = __syncthreads_or(pred);
    if (!any) return;                          // zeros already stored == answer

    // -------- rare general path: replay the masked LSTM up to t_end --------
    __shared__ int   acts[T];
    __shared__ float h0s[U];
    __shared__ float h1s[U];
    __shared__ float zbuf[Z];
    __shared__ float embs[E];

    for (int t = j; t < t_end; t += 256)
        acts[t] = (x[(size_t)b * T + t] == 0);

    embs[j] = emb[j];            // embedding row of token 0
    h0s[j]  = 0.0f;
    h1s[j]  = 0.0f;
    __syncthreads();             // also orders the zero-fill stores block-wide

    // Constant layer-0 x-contribution: xz = emb[0,:] @ k0 + b0.
    // Thread j owns gate columns 4j..4j+3 (float4 across Z).
    float4 xz = reinterpret_cast<const float4*>(b0)[j];
    for (int e = 0; e < E; e++) {
        const float  ev = embs[e];
        const float4 kv = reinterpret_cast<const float4*>(k0 + (size_t)e * Z)[j];
        xz.x += ev * kv.x; xz.y += ev * kv.y; xz.z += ev * kv.z; xz.w += ev * kv.w;
    }
    const float4 b1v = reinterpret_cast<const float4*>(b1)[j];

    float c0 = 0.0f, c1 = 0.0f;

    for (int t = 0; t < t_end; t++) {
        if (acts[t]) {
            // ---- layer 0: z = xz + h0 @ r0 ----
            float4 z = xz;
            #pragma unroll 4
            for (int k = 0; k < U; k++) {
                const float  hv = h0s[k];
                const float4 rv = reinterpret_cast<const float4*>(r0 + (size_t)k * Z)[j];
                z.x += hv * rv.x; z.y += hv * rv.y; z.z += hv * rv.z; z.w += hv * rv.w;
            }
            reinterpret_cast<float4*>(zbuf)[j] = z;
            __syncthreads();
            {
                const float ig = sigm (zbuf[0 * U + j]);
                const float fg = sigm (zbuf[1 * U + j]);
                const float gg = tanhf(zbuf[2 * U + j]);
                const float og = sigm (zbuf[3 * U + j]);
                c0 = fg * c0 + ig * gg;
                __syncthreads();               // matvec reads of h0s fully done
                h0s[j] = og * tanhf(c0);
            }
            __syncthreads();

            // ---- layer 1: w = b1 + h0 @ k1 + h1 @ r1 ----
            float4 w = b1v;
            #pragma unroll 2
            for (int k = 0; k < U; k++) {
                const float  h0v = h0s[k];
                const float  h1v = h1s[k];
                const float4 kv = reinterpret_cast<const float4*>(k1 + (size_t)k * Z)[j];
                const float4 rv = reinterpret_cast<const float4*>(r1 + (size_t)k * Z)[j];
                w.x += h0v * kv.x + h1v * rv.x;
                w.y += h0v * kv.y + h1v * rv.y;
                w.z += h0v * kv.z + h1v * rv.z;
                w.w += h0v * kv.w + h1v * rv.w;
            }
            __syncthreads();                   // prior zbuf reads done
            reinterpret_cast<float4*>(zbuf)[j] = w;
            __syncthreads();
            {
                const float ig = sigm (zbuf[0 * U + j]);
                const float fg = sigm (zbuf[1 * U + j]);
                const float gg = tanhf(zbuf[2 * U + j]);
                const float og = sigm (zbuf[3 * U + j]);
                c1 = fg * c1 + ig * gg;
                __syncthreads();               // matvec reads of h1s fully done
                h1s[j] = og * tanhf(c1);
            }
            __syncthreads();
        }
        if (t >= t0)
            out[(size_t)b * T * U + (size_t)t * U + j] = h1s[j];
    }

    if (chunk == NCHUNK - 1)                   // ran the full sequence
        out[(size_t)B * T * U + (size_t)b * U + j] = h1s[j];
}

extern "C" void kernel_launch(void* const* d_in, const int* in_sizes, int n_in,
                              void* d_out, int out_size)
{
    const int*   x   = (const int*)  d_in[0];
    const float* emb = (const float*)d_in[1];
    const float* k0  = (const float*)d_in[2];
    const float* r0  = (const float*)d_in[3];
    const float* b0  = (const float*)d_in[4];
    const float* k1  = (const float*)d_in[5];
    const float* r1  = (const float*)d_in[6];
    const float* b1  = (const float*)d_in[7];
    float* out = (float*)d_out;

    lstm_fused_kernel<<<B * NCHUNK, 256>>>(x, emb, k0, r0, b0, k1, r1, b1, out);
}

// round 10
// speedup vs baseline: 1.0719x; 1.0719x over previous
#include <cuda_runtime.h>
#include <math.h>

#define B 64
#define T 512
#define E 256
#define U 256
#define Z 1024      /* 4*U */
#define CHUNK 128
#define NCHUNK (T / CHUNK)   /* 4 */

__device__ __forceinline__ float sigm(float v) { return 1.0f / (1.0f + expf(-v)); }

// Converged design (R1-R9 evidence): output is 33.5MB of mandatory writes
// against a shared ~4.1 TB/s L2 write-commit wall (STG == TMA == CE memset,
// proven shared by the R7 concurrency test). Kernel floor ~8.2us + ~2us graph
// gap. Structure: STORE FIRST, CHECK LATER, one CTA per (batch, 128-step
// chunk), 256 CTAs — halves the prologue replication vs the 512-CTA variant.
//
// Keras masked-LSTM semantics: state updates ONLY where token == 0 (mask
// True); elsewhere h/c carry and out[b,t] is the carried h1. Every CTA
// unconditionally zero-fills its chunk while its token int4 load is in
// flight; only CTAs whose prefix [0, t_end) contains a zero token replay the
// masked LSTM and overwrite (exact for arbitrary inputs; block-wide
// __syncthreads() orders zero-fill stores before replay stores).
__global__ __launch_bounds__(256)
void lstm_fused_kernel(const int*   __restrict__ x,
                       const float* __restrict__ emb,
                       const float* __restrict__ k0,
                       const float* __restrict__ r0,
                       const float* __restrict__ b0,
                       const float* __restrict__ k1,
                       const float* __restrict__ r1,
                       const float* __restrict__ b1,
                       float*       __restrict__ out)
{
    const int b     = blockIdx.x >> 2;
    const int chunk = blockIdx.x & (NCHUNK - 1);
    const int t0    = chunk * CHUNK;
    const int t_end = t0 + CHUNK;
    const int j     = threadIdx.x;            // 0..255

    // Kick off the token load immediately (consumed after the stores).
    const int n4 = t_end >> 2;                 // 32..128 int4 words
    int4 tv = make_int4(1, 1, 1, 1);
    if (j < n4)
        tv = reinterpret_cast<const int4*>(x + (size_t)b * T)[j];

    // Unconditional zero-fill: 128*256 floats = 8192 f4 / 256 thr = 32 stores.
    {
        const float4 zv = make_float4(0.f, 0.f, 0.f, 0.f);
        float4* dst = reinterpret_cast<float4*>(out + (size_t)b * T * U + (size_t)t0 * U)
                      + j;
        #pragma unroll
        for (int i = 0; i < 32; i++)
            __stcs(dst + i * 256, zv);
        if (chunk == NCHUNK - 1 && j < U / 4) {
            float4* hdst = reinterpret_cast<float4*>(out + (size_t)B * T * U + (size_t)b * U);
            __stcs(hdst + j, zv);
        }
    }

    // Resolve the predicate: any zero token in [0, t_end)?
    const int pred = (j < n4) ? ((tv.x == 0) | (tv.y == 0) | (tv.z == 0) | (tv.w == 0)) : 0;
    const int any = __syncthreads_or(pred);
    if (!any) return;                          // zeros already stored == answer

    // -------- rare general path: replay the masked LSTM up to t_end --------
    __shared__ int   acts[T];
    __shared__ float h0s[U];
    __shared__ float h1s[U];
    __shared__ float zbuf[Z];
    __shared__ float embs[E];

    for (int t = j; t < t_end; t += 256)
        acts[t] = (x[(size_t)b * T + t] == 0);

    embs[j] = emb[j];            // embedding row of token 0
    h0s[j]  = 0.0f;
    h1s[j]  = 0.0f;
    __syncthreads();             // also orders the zero-fill stores block-wide

    // Constant layer-0 x-contribution: xz = emb[0,:] @ k0 + b0.
    // Thread j owns gate columns 4j..4j+3 (float4 across Z).
    float4 xz = reinterpret_cast<const float4*>(b0)[j];
    for (int e = 0; e < E; e++) {
        const float  ev = embs[e];
        const float4 kv = reinterpret_cast<const float4*>(k0 + (size_t)e * Z)[j];
        xz.x += ev * kv.x; xz.y += ev * kv.y; xz.z += ev * kv.z; xz.w += ev * kv.w;
    }
    const float4 b1v = reinterpret_cast<const float4*>(b1)[j];

    float c0 = 0.0f, c1 = 0.0f;

    for (int t = 0; t < t_end; t++) {
        if (acts[t]) {
            // ---- layer 0: z = xz + h0 @ r0 ----
            float4 z = xz;
            #pragma unroll 4
            for (int k = 0; k < U; k++) {
                const float  hv = h0s[k];
                const float4 rv = reinterpret_cast<const float4*>(r0 + (size_t)k * Z)[j];
                z.x += hv * rv.x; z.y += hv * rv.y; z.z += hv * rv.z; z.w += hv * rv.w;
            }
            reinterpret_cast<float4*>(zbuf)[j] = z;
            __syncthreads();
            {
                const float ig = sigm (zbuf[0 * U + j]);
                const float fg = sigm (zbuf[1 * U + j]);
                const float gg = tanhf(zbuf[2 * U + j]);
                const float og = sigm (zbuf[3 * U + j]);
                c0 = fg * c0 + ig * gg;
                __syncthreads();               // matvec reads of h0s fully done
                h0s[j] = og * tanhf(c0);
            }
            __syncthreads();

            // ---- layer 1: w = b1 + h0 @ k1 + h1 @ r1 ----
            float4 w = b1v;
            #pragma unroll 2
            for (int k = 0; k < U; k++) {
                const float  h0v = h0s[k];
                const float  h1v = h1s[k];
                const float4 kv = reinterpret_cast<const float4*>(k1 + (size_t)k * Z)[j];
                const float4 rv = reinterpret_cast<const float4*>(r1 + (size_t)k * Z)[j];
                w.x += h0v * kv.x + h1v * rv.x;
                w.y += h0v * kv.y + h1v * rv.y;
                w.z += h0v * kv.z + h1v * rv.z;
                w.w += h0v * kv.w + h1v * rv.w;
            }
            __syncthreads();                   // prior zbuf reads done
            reinterpret_cast<float4*>(zbuf)[j] = w;
            __syncthreads();
            {
                const float ig = sigm (zbuf[0 * U + j]);
                const float fg = sigm (zbuf[1 * U + j]);
                const float gg = tanhf(zbuf[2 * U + j]);
                const float og = sigm (zbuf[3 * U + j]);
                c1 = fg * c1 + ig * gg;
                __syncthreads();               // matvec reads of h1s fully done
                h1s[j] = og * tanhf(c1);
            }
            __syncthreads();
        }
        if (t >= t0)
            out[(size_t)b * T * U + (size_t)t * U + j] = h1s[j];
    }

    if (chunk == NCHUNK - 1)                   // ran the full sequence
        out[(size_t)B * T * U + (size_t)b * U + j] = h1s[j];
}

extern "C" void kernel_launch(void* const* d_in, const int* in_sizes, int n_in,
                              void* d_out, int out_size)
{
    const int*   x   = (const int*)  d_in[0];
    const float* emb = (const float*)d_in[1];
    const float* k0  = (const float*)d_in[2];
    const float* r0  = (const float*)d_in[3];
    const float* b0  = (const float*)d_in[4];
    const float* k1  = (const float*)d_in[5];
    const float* r1  = (const float*)d_in[6];
    const float* b1  = (const float*)d_in[7];
    float* out = (float*)d_out;

    lstm_fused_kernel<<<B * NCHUNK, 256>>>(x, emb, k0, r0, b0, k1, r1, b1, out);
}